// round 2
// baseline (speedup 1.0000x reference)
#include <cuda_runtime.h>
#include <math.h>
#include <float.h>

#define NN 80000
#define EE 1280000
#define GG 64
#define CINC 128
#define DD 64
#define NHID 5
#define NB_SCAN ((NN + 1023) / 1024)

// ---------------- scratch (device globals; no allocation allowed) ----------
__device__ int   g_deg[NN];
__device__ float g_dinv[NN];
__device__ int   g_rowptr[NN + 1];
__device__ int   g_cursor[NN];
__device__ int   g_col[EE];
__device__ float g_wnorm[EE];
__device__ float g_h0[NN * DD];   // GEMM output (pre-aggregation)
__device__ float g_h1[NN * DD];   // aggregation output (layer output)
__device__ int   g_bsum[NB_SCAN];
__device__ int   g_boff[NB_SCAN];
__device__ float g_psum[GG * DD];
__device__ float g_pmax[GG * DD];

// ---------------- CSR build ----------------
__global__ void zero_deg_kernel() {
    int i = blockIdx.x * blockDim.x + threadIdx.x;
    if (i < NN) g_deg[i] = 0;
}

__global__ void count_deg_kernel(const int* __restrict__ ei) {
    int e = blockIdx.x * blockDim.x + threadIdx.x;
    if (e < EE) atomicAdd(&g_deg[ei[EE + e]], 1);
}

__global__ void dinv_kernel() {
    int i = blockIdx.x * blockDim.x + threadIdx.x;
    if (i < NN) g_dinv[i] = rsqrtf((float)(g_deg[i] + 1));  // +1 self loop
}

// inclusive scan per 1024-block, store exclusive values + block sums
__global__ void scanA_kernel() {
    __shared__ int sh[1024];
    int gid = blockIdx.x * 1024 + threadIdx.x;
    int v = (gid < NN) ? g_deg[gid] : 0;
    sh[threadIdx.x] = v;
    __syncthreads();
    #pragma unroll
    for (int off = 1; off < 1024; off <<= 1) {
        int t = (threadIdx.x >= off) ? sh[threadIdx.x - off] : 0;
        __syncthreads();
        sh[threadIdx.x] += t;
        __syncthreads();
    }
    if (gid < NN) g_rowptr[gid] = sh[threadIdx.x] - v;  // exclusive within block
    if (threadIdx.x == 1023) g_bsum[blockIdx.x] = sh[1023];
}

__global__ void scanB_kernel() {
    if (threadIdx.x == 0 && blockIdx.x == 0) {
        int acc = 0;
        for (int i = 0; i < NB_SCAN; i++) {
            int t = g_bsum[i];
            g_boff[i] = acc;
            acc += t;
        }
    }
}

__global__ void scanC_kernel() {
    int gid = blockIdx.x * 1024 + threadIdx.x;
    if (gid < NN) {
        int r = g_rowptr[gid] + g_boff[blockIdx.x];
        g_rowptr[gid] = r;
        g_cursor[gid] = r;
    }
    if (gid == 0) g_rowptr[NN] = EE;
}

__global__ void scatter_kernel(const int* __restrict__ ei) {
    int e = blockIdx.x * blockDim.x + threadIdx.x;
    if (e < EE) {
        int s = ei[e];
        int d = ei[EE + e];
        int pos = atomicAdd(&g_cursor[d], 1);
        g_col[pos]   = s;
        g_wnorm[pos] = g_dinv[s] * g_dinv[d];
    }
}

// ---------------- GEMM: g_h0[N,64] = X[N,K] @ W[K,64] ----------------
// FROM_EXT=true  : read rows from external pointer X (layer 0, K=CINC)
// FROM_EXT=false : read rows from g_h1 (hidden layers, K=DD)
template <int K, bool FROM_EXT>
__global__ void gemm_kernel(const float* __restrict__ X,
                            const float* __restrict__ W) {
    __shared__ float Ws[K * 64];
    for (int i = threadIdx.x; i < K * 64; i += blockDim.x) Ws[i] = W[i];
    __syncthreads();

    int row = blockIdx.x * blockDim.x + threadIdx.x;
    if (row >= NN) return;

    float acc[64];
    #pragma unroll
    for (int d = 0; d < 64; d++) acc[d] = 0.f;

    const float* xr = FROM_EXT ? (X + (size_t)row * K) : (g_h1 + (size_t)row * K);
    #pragma unroll 4
    for (int k = 0; k < K; k++) {
        float xv = __ldg(&xr[k]);
        const float4* wr = reinterpret_cast<const float4*>(&Ws[k * 64]);
        #pragma unroll
        for (int d4 = 0; d4 < 16; d4++) {
            float4 w4 = wr[d4];
            acc[d4 * 4 + 0] += xv * w4.x;
            acc[d4 * 4 + 1] += xv * w4.y;
            acc[d4 * 4 + 2] += xv * w4.z;
            acc[d4 * 4 + 3] += xv * w4.w;
        }
    }
    float4* yr = reinterpret_cast<float4*>(g_h0 + (size_t)row * 64);
    #pragma unroll
    for (int d4 = 0; d4 < 16; d4++) {
        float4 o;
        o.x = acc[d4 * 4 + 0];
        o.y = acc[d4 * 4 + 1];
        o.z = acc[d4 * 4 + 2];
        o.w = acc[d4 * 4 + 3];
        yr[d4] = o;
    }
}

// ---------------- aggregation: warp per node, CSR gather (g_h0 -> g_h1) ----
__global__ void aggregate_kernel(const float* __restrict__ bias, int relu) {
    int node = blockIdx.x * (blockDim.x >> 5) + (threadIdx.x >> 5);
    int lane = threadIdx.x & 31;
    if (node >= NN) return;

    float dn = g_dinv[node];
    float selfw = dn * dn;
    float a0 = selfw * g_h0[(size_t)node * 64 + lane];
    float a1 = selfw * g_h0[(size_t)node * 64 + 32 + lane];

    int beg = g_rowptr[node];
    int end = g_rowptr[node + 1];
    for (int e = beg; e < end; e++) {
        int   s  = g_col[e];
        float ww = g_wnorm[e];
        const float* hr = g_h0 + (size_t)s * 64;
        a0 += ww * __ldg(&hr[lane]);
        a1 += ww * __ldg(&hr[32 + lane]);
    }
    a0 += bias[lane];
    a1 += bias[32 + lane];
    if (relu) { a0 = fmaxf(a0, 0.f); a1 = fmaxf(a1, 0.f); }
    g_h1[(size_t)node * 64 + lane]      = a0;
    g_h1[(size_t)node * 64 + 32 + lane] = a1;
}

// ---------------- pooling ----------------
__global__ void pool_init_kernel() {
    int i = blockIdx.x * blockDim.x + threadIdx.x;
    if (i < GG * DD) {
        g_psum[i] = 0.f;
        g_pmax[i] = -FLT_MAX;
    }
}

__device__ __forceinline__ void atomicMaxF(float* addr, float val) {
    if (val >= 0.f)
        atomicMax((int*)addr, __float_as_int(val));
    else
        atomicMin((unsigned int*)addr, __float_as_uint(val));
}

__global__ void pool_kernel(const int* __restrict__ batch) {
    int idx = blockIdx.x * blockDim.x + threadIdx.x;
    if (idx < NN * DD) {
        int node = idx >> 6;
        int d    = idx & 63;
        int g    = batch[node];
        float v  = g_h1[idx];
        atomicAdd(&g_psum[g * 64 + d], v);
        atomicMaxF(&g_pmax[g * 64 + d], v);
    }
}

// ---------------- MLP head: one block per graph ----------------
__global__ void head_kernel(const float* __restrict__ lin1_w, const float* __restrict__ lin1_b,
                            const float* __restrict__ lin2_w, const float* __restrict__ lin2_b,
                            const float* __restrict__ lin3_w, const float* __restrict__ lin3_b,
                            float* __restrict__ out) {
    int g = blockIdx.x;
    int d = threadIdx.x;   // 0..63
    __shared__ float feat[128];
    __shared__ float s1[64];
    __shared__ float s2[64];
    __shared__ float red[64];

    feat[d]      = g_psum[g * 64 + d];
    feat[64 + d] = g_pmax[g * 64 + d];
    __syncthreads();

    float a = lin1_b[d];
    #pragma unroll 8
    for (int k = 0; k < 128; k++) a += feat[k] * lin1_w[k * 64 + d];
    s1[d] = fmaxf(a, 0.f);
    __syncthreads();

    float b = lin2_b[d];
    #pragma unroll 8
    for (int k = 0; k < 64; k++) b += s1[k] * lin2_w[k * 64 + d];
    s2[d] = fmaxf(b, 0.f);
    __syncthreads();

    red[d] = s2[d] * lin3_w[d];
    __syncthreads();
    #pragma unroll
    for (int off = 32; off > 0; off >>= 1) {
        if (d < off) red[d] += red[d + off];
        __syncthreads();
    }
    if (d == 0) out[g] = red[0] + lin3_b[0];
}

// ---------------- launch ----------------
extern "C" void kernel_launch(void* const* d_in, const int* in_sizes, int n_in,
                              void* d_out, int out_size) {
    const float* x      = (const float*)d_in[0];
    const int*   ei     = (const int*)d_in[1];
    const int*   batch  = (const int*)d_in[2];
    const float* W_in   = (const float*)d_in[3];
    const float* b_in   = (const float*)d_in[4];
    const float* W_hid  = (const float*)d_in[5];
    const float* b_hid  = (const float*)d_in[6];
    const float* lin1_w = (const float*)d_in[7];
    const float* lin1_b = (const float*)d_in[8];
    const float* lin2_w = (const float*)d_in[9];
    const float* lin2_b = (const float*)d_in[10];
    const float* lin3_w = (const float*)d_in[11];
    const float* lin3_b = (const float*)d_in[12];
    float* out = (float*)d_out;

    // CSR build
    zero_deg_kernel<<<(NN + 255) / 256, 256>>>();
    count_deg_kernel<<<(EE + 255) / 256, 256>>>(ei);
    dinv_kernel<<<(NN + 255) / 256, 256>>>();
    scanA_kernel<<<NB_SCAN, 1024>>>();
    scanB_kernel<<<1, 32>>>();
    scanC_kernel<<<NB_SCAN, 1024>>>();
    scatter_kernel<<<(EE + 255) / 256, 256>>>(ei);

    const int gemm_blocks = (NN + 255) / 256;
    const int agg_blocks  = (NN + 7) / 8;   // 8 warps per block

    // layer 0: CIN -> D, ReLU
    gemm_kernel<CINC, true><<<gemm_blocks, 256>>>(x, W_in);
    aggregate_kernel<<<agg_blocks, 256>>>(b_in, 1);

    // hidden layers
    for (int i = 0; i < NHID; i++) {
        gemm_kernel<DD, false><<<gemm_blocks, 256>>>(nullptr, W_hid + (size_t)i * DD * DD);
        aggregate_kernel<<<agg_blocks, 256>>>(b_hid + (size_t)i * DD,
                                              (i < NHID - 1) ? 1 : 0);
    }

    // pooling
    pool_init_kernel<<<(GG * DD + 255) / 256, 256>>>();
    pool_kernel<<<(NN * DD + 255) / 256, 256>>>(batch);

    // head
    head_kernel<<<GG, 64>>>(lin1_w, lin1_b, lin2_w, lin2_b, lin3_w, lin3_b, out);
}

// round 3
// speedup vs baseline: 1.4840x; 1.4840x over previous
#include <cuda_runtime.h>
#include <math.h>
#include <float.h>

#define NN 80000
#define EE 1280000
#define GG 64
#define CINC 128
#define DD 64
#define NHID 5
#define NB_SCAN ((NN + 1023) / 1024)

typedef unsigned long long u64t;

__device__ __forceinline__ u64t fma2(u64t a, u64t b, u64t c) {
    u64t d;
    asm("fma.rn.f32x2 %0, %1, %2, %3;" : "=l"(d) : "l"(a), "l"(b), "l"(c));
    return d;
}

// ---------------- scratch ----------------
__device__ int   g_deg[NN];
__device__ float g_dinv[NN];
__device__ int   g_rowptr[NN + 1];
__device__ int   g_cursor[NN];
__device__ int2  g_edge[EE];      // {src, wnorm bits}
__device__ float g_h0[NN * DD];   // GEMM output (pre-aggregation)
__device__ float g_h1[NN * DD];   // aggregation output
__device__ int   g_bsum[NB_SCAN];
__device__ int   g_boff[NB_SCAN];
__device__ float g_psum[GG * DD];
__device__ float g_pmax[GG * DD];

// ---------------- CSR build ----------------
__global__ void zero_deg_kernel() {
    int i = blockIdx.x * blockDim.x + threadIdx.x;
    if (i < NN) g_deg[i] = 0;
}

__global__ void count_deg_kernel(const int* __restrict__ ei) {
    int e = blockIdx.x * blockDim.x + threadIdx.x;
    if (e < EE) atomicAdd(&g_deg[ei[EE + e]], 1);
}

__global__ void dinv_kernel() {
    int i = blockIdx.x * blockDim.x + threadIdx.x;
    if (i < NN) g_dinv[i] = rsqrtf((float)(g_deg[i] + 1));
}

__global__ void scanA_kernel() {
    __shared__ int sh[1024];
    int gid = blockIdx.x * 1024 + threadIdx.x;
    int v = (gid < NN) ? g_deg[gid] : 0;
    sh[threadIdx.x] = v;
    __syncthreads();
    #pragma unroll
    for (int off = 1; off < 1024; off <<= 1) {
        int t = (threadIdx.x >= off) ? sh[threadIdx.x - off] : 0;
        __syncthreads();
        sh[threadIdx.x] += t;
        __syncthreads();
    }
    if (gid < NN) g_rowptr[gid] = sh[threadIdx.x] - v;
    if (threadIdx.x == 1023) g_bsum[blockIdx.x] = sh[1023];
}

__global__ void scanB_kernel() {
    if (threadIdx.x == 0 && blockIdx.x == 0) {
        int acc = 0;
        for (int i = 0; i < NB_SCAN; i++) {
            int t = g_bsum[i];
            g_boff[i] = acc;
            acc += t;
        }
    }
}

__global__ void scanC_kernel() {
    int gid = blockIdx.x * 1024 + threadIdx.x;
    if (gid < NN) {
        int r = g_rowptr[gid] + g_boff[blockIdx.x];
        g_rowptr[gid] = r;
        g_cursor[gid] = r;
    }
    if (gid == 0) g_rowptr[NN] = EE;
}

__global__ void scatter_kernel(const int* __restrict__ ei) {
    int e = blockIdx.x * blockDim.x + threadIdx.x;
    if (e < EE) {
        int s = ei[e];
        int d = ei[EE + e];
        int pos = atomicAdd(&g_cursor[d], 1);
        float w = g_dinv[s] * g_dinv[d];
        g_edge[pos] = make_int2(s, __float_as_int(w));
    }
}

// ---------------- GEMM: g_h0[N,64] = X[N,K] @ W[K,64], packed f32x2 --------
template <int K, bool FROM_EXT>
__global__ void gemm_kernel(const float* __restrict__ X,
                            const float* __restrict__ W) {
    __shared__ u64t Ws[K * 32];
    {
        const u64t* Wp = reinterpret_cast<const u64t*>(W);
        for (int i = threadIdx.x; i < K * 32; i += blockDim.x) Ws[i] = Wp[i];
    }
    __syncthreads();

    int row = blockIdx.x * blockDim.x + threadIdx.x;
    if (row >= NN) return;

    u64t acc[32];
    #pragma unroll
    for (int j = 0; j < 32; j++) acc[j] = 0ull;

    const float* xbase = FROM_EXT ? X : (const float*)g_h1;
    const float4* xr = reinterpret_cast<const float4*>(xbase + (size_t)row * K);

    #pragma unroll 2
    for (int k4 = 0; k4 < K / 4; k4++) {
        float4 xv4 = __ldg(&xr[k4]);
        float xs[4] = {xv4.x, xv4.y, xv4.z, xv4.w};
        #pragma unroll
        for (int kk = 0; kk < 4; kk++) {
            u64t xv2;
            unsigned xb = __float_as_uint(xs[kk]);
            asm("mov.b64 %0, {%1, %1};" : "=l"(xv2) : "r"(xb));
            const ulonglong2* wr =
                reinterpret_cast<const ulonglong2*>(&Ws[(k4 * 4 + kk) * 32]);
            #pragma unroll
            for (int j = 0; j < 16; j++) {
                ulonglong2 w2 = wr[j];
                acc[2 * j]     = fma2(w2.x, xv2, acc[2 * j]);
                acc[2 * j + 1] = fma2(w2.y, xv2, acc[2 * j + 1]);
            }
        }
    }

    ulonglong2* yr = reinterpret_cast<ulonglong2*>(g_h0 + (size_t)row * 64);
    #pragma unroll
    for (int j = 0; j < 16; j++) {
        ulonglong2 t;
        t.x = acc[2 * j];
        t.y = acc[2 * j + 1];
        yr[j] = t;
    }
}

// ---------------- aggregation: warp/node, float2 lanes ----------------
__global__ void aggregate_kernel(const float* __restrict__ bias, int relu) {
    int node = blockIdx.x * (blockDim.x >> 5) + (threadIdx.x >> 5);
    int lane = threadIdx.x & 31;
    if (node >= NN) return;

    const float2* h0 = reinterpret_cast<const float2*>(g_h0);

    float dn = g_dinv[node];
    float sw = dn * dn;
    float2 self = h0[(size_t)node * 32 + lane];
    float ax = sw * self.x;
    float ay = sw * self.y;

    int beg = g_rowptr[node];
    int end = g_rowptr[node + 1];
    #pragma unroll 4
    for (int e = beg; e < end; e++) {
        int2  ed = __ldg(&g_edge[e]);
        float ww = __int_as_float(ed.y);
        float2 hv = __ldg(&h0[(size_t)ed.x * 32 + lane]);
        ax += ww * hv.x;
        ay += ww * hv.y;
    }

    float2 bv = reinterpret_cast<const float2*>(bias)[lane];
    ax += bv.x;
    ay += bv.y;
    if (relu) { ax = fmaxf(ax, 0.f); ay = fmaxf(ay, 0.f); }
    reinterpret_cast<float2*>(g_h1)[(size_t)node * 32 + lane] =
        make_float2(ax, ay);
}

// ---------------- pooling ----------------
__global__ void pool_init_kernel() {
    int i = blockIdx.x * blockDim.x + threadIdx.x;
    if (i < GG * DD) {
        g_psum[i] = 0.f;
        g_pmax[i] = -FLT_MAX;
    }
}

__device__ __forceinline__ void atomicMaxF(float* addr, float val) {
    if (val >= 0.f)
        atomicMax((int*)addr, __float_as_int(val));
    else
        atomicMin((unsigned int*)addr, __float_as_uint(val));
}

__device__ __forceinline__ void pool_flush(int g, int lane, float2 s, float2 m) {
    atomicAdd(&g_psum[g * 64 + 2 * lane],     s.x);
    atomicAdd(&g_psum[g * 64 + 2 * lane + 1], s.y);
    atomicMaxF(&g_pmax[g * 64 + 2 * lane],     m.x);
    atomicMaxF(&g_pmax[g * 64 + 2 * lane + 1], m.y);
}

#define POOL_NPW 64   // nodes per warp
__global__ void pool_kernel(const int* __restrict__ batch) {
    int warp = blockIdx.x * (blockDim.x >> 5) + (threadIdx.x >> 5);
    int lane = threadIdx.x & 31;
    int n0 = warp * POOL_NPW;
    if (n0 >= NN) return;
    int n1 = min(n0 + POOL_NPW, NN);

    const float2* h1 = reinterpret_cast<const float2*>(g_h1);
    int curg = __ldg(&batch[n0]);
    float2 s = make_float2(0.f, 0.f);
    float2 m = make_float2(-FLT_MAX, -FLT_MAX);

    for (int node = n0; node < n1; node++) {
        int g = __ldg(&batch[node]);
        if (g != curg) {
            pool_flush(curg, lane, s, m);
            curg = g;
            s = make_float2(0.f, 0.f);
            m = make_float2(-FLT_MAX, -FLT_MAX);
        }
        float2 v = h1[(size_t)node * 32 + lane];
        s.x += v.x; s.y += v.y;
        m.x = fmaxf(m.x, v.x); m.y = fmaxf(m.y, v.y);
    }
    pool_flush(curg, lane, s, m);
}

// ---------------- MLP head ----------------
__global__ void head_kernel(const float* __restrict__ lin1_w, const float* __restrict__ lin1_b,
                            const float* __restrict__ lin2_w, const float* __restrict__ lin2_b,
                            const float* __restrict__ lin3_w, const float* __restrict__ lin3_b,
                            float* __restrict__ out) {
    int g = blockIdx.x;
    int d = threadIdx.x;   // 0..63
    __shared__ float feat[128];
    __shared__ float s1[64];
    __shared__ float s2[64];
    __shared__ float red[64];

    feat[d]      = g_psum[g * 64 + d];
    feat[64 + d] = g_pmax[g * 64 + d];
    __syncthreads();

    float a = lin1_b[d];
    #pragma unroll 8
    for (int k = 0; k < 128; k++) a += feat[k] * lin1_w[k * 64 + d];
    s1[d] = fmaxf(a, 0.f);
    __syncthreads();

    float b = lin2_b[d];
    #pragma unroll 8
    for (int k = 0; k < 64; k++) b += s1[k] * lin2_w[k * 64 + d];
    s2[d] = fmaxf(b, 0.f);
    __syncthreads();

    red[d] = s2[d] * lin3_w[d];
    __syncthreads();
    #pragma unroll
    for (int off = 32; off > 0; off >>= 1) {
        if (d < off) red[d] += red[d + off];
        __syncthreads();
    }
    if (d == 0) out[g] = red[0] + lin3_b[0];
}

// ---------------- launch ----------------
extern "C" void kernel_launch(void* const* d_in, const int* in_sizes, int n_in,
                              void* d_out, int out_size) {
    const float* x      = (const float*)d_in[0];
    const int*   ei     = (const int*)d_in[1];
    const int*   batch  = (const int*)d_in[2];
    const float* W_in   = (const float*)d_in[3];
    const float* b_in   = (const float*)d_in[4];
    const float* W_hid  = (const float*)d_in[5];
    const float* b_hid  = (const float*)d_in[6];
    const float* lin1_w = (const float*)d_in[7];
    const float* lin1_b = (const float*)d_in[8];
    const float* lin2_w = (const float*)d_in[9];
    const float* lin2_b = (const float*)d_in[10];
    const float* lin3_w = (const float*)d_in[11];
    const float* lin3_b = (const float*)d_in[12];
    float* out = (float*)d_out;

    // CSR build
    zero_deg_kernel<<<(NN + 255) / 256, 256>>>();
    count_deg_kernel<<<(EE + 255) / 256, 256>>>(ei);
    dinv_kernel<<<(NN + 255) / 256, 256>>>();
    scanA_kernel<<<NB_SCAN, 1024>>>();
    scanB_kernel<<<1, 32>>>();
    scanC_kernel<<<NB_SCAN, 1024>>>();
    scatter_kernel<<<(EE + 255) / 256, 256>>>(ei);

    const int gemm_blocks = (NN + 255) / 256;
    const int agg_blocks  = (NN + 7) / 8;

    // layer 0
    gemm_kernel<CINC, true><<<gemm_blocks, 256>>>(x, W_in);
    aggregate_kernel<<<agg_blocks, 256>>>(b_in, 1);

    // hidden layers
    for (int i = 0; i < NHID; i++) {
        gemm_kernel<DD, false><<<gemm_blocks, 256>>>(nullptr, W_hid + (size_t)i * DD * DD);
        aggregate_kernel<<<agg_blocks, 256>>>(b_hid + (size_t)i * DD,
                                              (i < NHID - 1) ? 1 : 0);
    }

    // pooling
    pool_init_kernel<<<(GG * DD + 255) / 256, 256>>>();
    {
        int warps = (NN + POOL_NPW - 1) / POOL_NPW;
        int blocks = (warps + 7) / 8;
        pool_kernel<<<blocks, 256>>>(batch);
    }

    // head
    head_kernel<<<GG, 64>>>(lin1_w, lin1_b, lin2_w, lin2_b, lin3_w, lin3_b, out);
}

// round 4
// speedup vs baseline: 1.5571x; 1.0493x over previous
#include <cuda_runtime.h>
#include <cuda_fp16.h>
#include <math.h>
#include <float.h>

#define NN 80000
#define EE 1280000
#define GG 64
#define CINC 128
#define DD 64
#define NHID 5
#define NB_SCAN ((NN + 1023) / 1024)

typedef unsigned long long u64t;

__device__ __forceinline__ u64t fma2(u64t a, u64t b, u64t c) {
    u64t d;
    asm("fma.rn.f32x2 %0, %1, %2, %3;" : "=l"(d) : "l"(a), "l"(b), "l"(c));
    return d;
}

// ---------------- scratch ----------------
__device__ int    g_deg[NN];
__device__ float  g_dinv[NN];
__device__ int    g_rowptr[NN + 1];
__device__ int    g_cursor[NN];
__device__ int2   g_edge[EE];        // {src, wnorm bits}
__device__ __half2 g_h0h[NN * 32];   // GEMM output (fp16, gather source)
__device__ float  g_h1[NN * DD];     // aggregation output (fp32)
__device__ int    g_bsum[NB_SCAN];
__device__ int    g_boff[NB_SCAN];
__device__ float  g_psum[GG * DD];
__device__ float  g_pmax[GG * DD];

// ---------------- CSR build ----------------
__global__ void zero_deg_kernel() {
    int i = blockIdx.x * blockDim.x + threadIdx.x;
    if (i < NN) g_deg[i] = 0;
}

__global__ void count_deg_kernel(const int* __restrict__ ei) {
    int e = blockIdx.x * blockDim.x + threadIdx.x;
    if (e < EE) atomicAdd(&g_deg[ei[EE + e]], 1);
}

// per-block scan + dinv (fused)
__global__ void scanA_kernel() {
    __shared__ int sh[1024];
    int gid = blockIdx.x * 1024 + threadIdx.x;
    int v = (gid < NN) ? g_deg[gid] : 0;
    if (gid < NN) g_dinv[gid] = rsqrtf((float)(v + 1));
    sh[threadIdx.x] = v;
    __syncthreads();
    #pragma unroll
    for (int off = 1; off < 1024; off <<= 1) {
        int t = (threadIdx.x >= off) ? sh[threadIdx.x - off] : 0;
        __syncthreads();
        sh[threadIdx.x] += t;
        __syncthreads();
    }
    if (gid < NN) g_rowptr[gid] = sh[threadIdx.x] - v;
    if (threadIdx.x == 1023) g_bsum[blockIdx.x] = sh[1023];
}

// parallel scan of block sums (NB_SCAN=79 <= 128)
__global__ void scanB_kernel() {
    __shared__ int sh[128];
    int t = threadIdx.x;
    int v = (t < NB_SCAN) ? g_bsum[t] : 0;
    sh[t] = v;
    __syncthreads();
    #pragma unroll
    for (int off = 1; off < 128; off <<= 1) {
        int u = (t >= off) ? sh[t - off] : 0;
        __syncthreads();
        sh[t] += u;
        __syncthreads();
    }
    if (t < NB_SCAN) g_boff[t] = sh[t] - v;  // exclusive
}

__global__ void scanC_kernel() {
    int gid = blockIdx.x * 1024 + threadIdx.x;
    if (gid < NN) {
        int r = g_rowptr[gid] + g_boff[blockIdx.x];
        g_rowptr[gid] = r;
        g_cursor[gid] = r;
    }
    if (gid == 0) g_rowptr[NN] = EE;
}

__global__ void scatter_kernel(const int* __restrict__ ei) {
    int e = blockIdx.x * blockDim.x + threadIdx.x;
    if (e < EE) {
        int s = ei[e];
        int d = ei[EE + e];
        int pos = atomicAdd(&g_cursor[d], 1);
        float w = g_dinv[s] * g_dinv[d];
        g_edge[pos] = make_int2(s, __float_as_int(w));
    }
}

// ------ GEMM: g_h0h[N,64](fp16) = X[N,K](fp32) @ W[K,64], packed f32x2 -----
template <int K, bool FROM_EXT>
__global__ void gemm_kernel(const float* __restrict__ X,
                            const float* __restrict__ W) {
    __shared__ u64t Ws[K * 32];
    {
        const u64t* Wp = reinterpret_cast<const u64t*>(W);
        for (int i = threadIdx.x; i < K * 32; i += blockDim.x) Ws[i] = Wp[i];
    }
    __syncthreads();

    int row = blockIdx.x * blockDim.x + threadIdx.x;
    if (row >= NN) return;

    u64t acc[32];
    #pragma unroll
    for (int j = 0; j < 32; j++) acc[j] = 0ull;

    const float* xbase = FROM_EXT ? X : (const float*)g_h1;
    const float4* xr = reinterpret_cast<const float4*>(xbase + (size_t)row * K);

    #pragma unroll 2
    for (int k4 = 0; k4 < K / 4; k4++) {
        float4 xv4 = __ldg(&xr[k4]);
        float xs[4] = {xv4.x, xv4.y, xv4.z, xv4.w};
        #pragma unroll
        for (int kk = 0; kk < 4; kk++) {
            u64t xv2;
            unsigned xb = __float_as_uint(xs[kk]);
            asm("mov.b64 %0, {%1, %1};" : "=l"(xv2) : "r"(xb));
            const ulonglong2* wr =
                reinterpret_cast<const ulonglong2*>(&Ws[(k4 * 4 + kk) * 32]);
            #pragma unroll
            for (int j = 0; j < 16; j++) {
                ulonglong2 w2 = wr[j];
                acc[2 * j]     = fma2(w2.x, xv2, acc[2 * j]);
                acc[2 * j + 1] = fma2(w2.y, xv2, acc[2 * j + 1]);
            }
        }
    }

    // convert to fp16 and store 128B row as 8 x uint4
    uint4* yr = reinterpret_cast<uint4*>(g_h0h + (size_t)row * 32);
    #pragma unroll
    for (int q = 0; q < 8; q++) {
        uint4 o;
        unsigned r[4];
        #pragma unroll
        for (int p = 0; p < 4; p++) {
            unsigned lo, hi;
            asm("mov.b64 {%0, %1}, %2;" : "=r"(lo), "=r"(hi) : "l"(acc[q * 4 + p]));
            float2 f = make_float2(__uint_as_float(lo), __uint_as_float(hi));
            __half2 h = __floats2half2_rn(f.x, f.y);
            r[p] = *reinterpret_cast<unsigned*>(&h);
        }
        o.x = r[0]; o.y = r[1]; o.z = r[2]; o.w = r[3];
        yr[q] = o;
    }
}

// ---------------- aggregation: warp/node, fp16 gather -> fp32 acc ----------
__global__ void aggregate_kernel(const float* __restrict__ bias, int relu) {
    int node = blockIdx.x * (blockDim.x >> 5) + (threadIdx.x >> 5);
    int lane = threadIdx.x & 31;
    if (node >= NN) return;

    float dn = g_dinv[node];
    float sw = dn * dn;
    float2 self = __half22float2(g_h0h[(size_t)node * 32 + lane]);
    float ax = sw * self.x;
    float ay = sw * self.y;

    int beg = g_rowptr[node];
    int end = g_rowptr[node + 1];
    #pragma unroll 4
    for (int e = beg; e < end; e++) {
        int2   ed = __ldg(&g_edge[e]);
        float  ww = __int_as_float(ed.y);
        __half2 hv2 = g_h0h[(size_t)ed.x * 32 + lane];
        float2 hv = __half22float2(hv2);
        ax += ww * hv.x;
        ay += ww * hv.y;
    }

    float2 bv = reinterpret_cast<const float2*>(bias)[lane];
    ax += bv.x;
    ay += bv.y;
    if (relu) { ax = fmaxf(ax, 0.f); ay = fmaxf(ay, 0.f); }
    reinterpret_cast<float2*>(g_h1)[(size_t)node * 32 + lane] =
        make_float2(ax, ay);
}

// ---------------- pooling ----------------
__global__ void pool_init_kernel() {
    int i = blockIdx.x * blockDim.x + threadIdx.x;
    if (i < GG * DD) {
        g_psum[i] = 0.f;
        g_pmax[i] = -FLT_MAX;
    }
}

__device__ __forceinline__ void atomicMaxF(float* addr, float val) {
    if (val >= 0.f)
        atomicMax((int*)addr, __float_as_int(val));
    else
        atomicMin((unsigned int*)addr, __float_as_uint(val));
}

__device__ __forceinline__ void pool_flush(int g, int lane, float2 s, float2 m) {
    atomicAdd(&g_psum[g * 64 + 2 * lane],     s.x);
    atomicAdd(&g_psum[g * 64 + 2 * lane + 1], s.y);
    atomicMaxF(&g_pmax[g * 64 + 2 * lane],     m.x);
    atomicMaxF(&g_pmax[g * 64 + 2 * lane + 1], m.y);
}

#define POOL_NPW 64   // nodes per warp
__global__ void pool_kernel(const int* __restrict__ batch) {
    int warp = blockIdx.x * (blockDim.x >> 5) + (threadIdx.x >> 5);
    int lane = threadIdx.x & 31;
    int n0 = warp * POOL_NPW;
    if (n0 >= NN) return;
    int n1 = min(n0 + POOL_NPW, NN);

    const float2* h1 = reinterpret_cast<const float2*>(g_h1);
    int curg = __ldg(&batch[n0]);
    float2 s = make_float2(0.f, 0.f);
    float2 m = make_float2(-FLT_MAX, -FLT_MAX);

    for (int node = n0; node < n1; node++) {
        int g = __ldg(&batch[node]);
        if (g != curg) {
            pool_flush(curg, lane, s, m);
            curg = g;
            s = make_float2(0.f, 0.f);
            m = make_float2(-FLT_MAX, -FLT_MAX);
        }
        float2 v = h1[(size_t)node * 32 + lane];
        s.x += v.x; s.y += v.y;
        m.x = fmaxf(m.x, v.x); m.y = fmaxf(m.y, v.y);
    }
    pool_flush(curg, lane, s, m);
}

// ---------------- MLP head ----------------
__global__ void head_kernel(const float* __restrict__ lin1_w, const float* __restrict__ lin1_b,
                            const float* __restrict__ lin2_w, const float* __restrict__ lin2_b,
                            const float* __restrict__ lin3_w, const float* __restrict__ lin3_b,
                            float* __restrict__ out) {
    int g = blockIdx.x;
    int d = threadIdx.x;   // 0..63
    __shared__ float feat[128];
    __shared__ float s1[64];
    __shared__ float s2[64];
    __shared__ float red[64];

    feat[d]      = g_psum[g * 64 + d];
    feat[64 + d] = g_pmax[g * 64 + d];
    __syncthreads();

    float a = lin1_b[d];
    #pragma unroll 8
    for (int k = 0; k < 128; k++) a += feat[k] * lin1_w[k * 64 + d];
    s1[d] = fmaxf(a, 0.f);
    __syncthreads();

    float b = lin2_b[d];
    #pragma unroll 8
    for (int k = 0; k < 64; k++) b += s1[k] * lin2_w[k * 64 + d];
    s2[d] = fmaxf(b, 0.f);
    __syncthreads();

    red[d] = s2[d] * lin3_w[d];
    __syncthreads();
    #pragma unroll
    for (int off = 32; off > 0; off >>= 1) {
        if (d < off) red[d] += red[d + off];
        __syncthreads();
    }
    if (d == 0) out[g] = red[0] + lin3_b[0];
}

// ---------------- launch ----------------
extern "C" void kernel_launch(void* const* d_in, const int* in_sizes, int n_in,
                              void* d_out, int out_size) {
    const float* x      = (const float*)d_in[0];
    const int*   ei     = (const int*)d_in[1];
    const int*   batch  = (const int*)d_in[2];
    const float* W_in   = (const float*)d_in[3];
    const float* b_in   = (const float*)d_in[4];
    const float* W_hid  = (const float*)d_in[5];
    const float* b_hid  = (const float*)d_in[6];
    const float* lin1_w = (const float*)d_in[7];
    const float* lin1_b = (const float*)d_in[8];
    const float* lin2_w = (const float*)d_in[9];
    const float* lin2_b = (const float*)d_in[10];
    const float* lin3_w = (const float*)d_in[11];
    const float* lin3_b = (const float*)d_in[12];
    float* out = (float*)d_out;

    // CSR build
    zero_deg_kernel<<<(NN + 255) / 256, 256>>>();
    count_deg_kernel<<<(EE + 255) / 256, 256>>>(ei);
    scanA_kernel<<<NB_SCAN, 1024>>>();
    scanB_kernel<<<1, 128>>>();
    scanC_kernel<<<NB_SCAN, 1024>>>();
    scatter_kernel<<<(EE + 255) / 256, 256>>>(ei);

    const int gemm_blocks = (NN + 255) / 256;
    const int agg_blocks  = (NN + 7) / 8;

    // layer 0
    gemm_kernel<CINC, true><<<gemm_blocks, 256>>>(x, W_in);
    aggregate_kernel<<<agg_blocks, 256>>>(b_in, 1);

    // hidden layers
    for (int i = 0; i < NHID; i++) {
        gemm_kernel<DD, false><<<gemm_blocks, 256>>>(nullptr, W_hid + (size_t)i * DD * DD);
        aggregate_kernel<<<agg_blocks, 256>>>(b_hid + (size_t)i * DD,
                                              (i < NHID - 1) ? 1 : 0);
    }

    // pooling
    pool_init_kernel<<<(GG * DD + 255) / 256, 256>>>();
    {
        int warps = (NN + POOL_NPW - 1) / POOL_NPW;
        int blocks = (warps + 7) / 8;
        pool_kernel<<<blocks, 256>>>(batch);
    }

    // head
    head_kernel<<<GG, 64>>>(lin1_w, lin1_b, lin2_w, lin2_b, lin3_w, lin3_b, out);
}

// round 5
// speedup vs baseline: 1.9388x; 1.2451x over previous
#include <cuda_runtime.h>
#include <cuda_fp16.h>
#include <math.h>
#include <float.h>

#define NN 80000
#define EE 1280000
#define GG 64
#define CINC 128
#define DD 64
#define NHID 5
#define NB_SCAN ((NN + 1023) / 1024)

typedef unsigned long long u64t;

__device__ __forceinline__ u64t fma2(u64t a, u64t b, u64t c) {
    u64t d;
    asm("fma.rn.f32x2 %0, %1, %2, %3;" : "=l"(d) : "l"(a), "l"(b), "l"(c));
    return d;
}
__device__ __forceinline__ u64t dup2(float x) {
    u64t r;
    unsigned xb = __float_as_uint(x);
    asm("mov.b64 %0, {%1, %1};" : "=l"(r) : "r"(xb));
    return r;
}

// ---------------- scratch ----------------
__device__ int    g_deg[NN];
__device__ float  g_dinv[NN];
__device__ int    g_rowptr[NN + 1];
__device__ int    g_cursor[NN];
__device__ int2   g_edge[EE];        // {src, wnorm bits}
__device__ __half2 g_h0h[NN * 32];   // GEMM output (fp16, gather source)
__device__ float  g_h1[NN * DD];     // aggregation output (fp32)
__device__ int    g_bsum[NB_SCAN];
__device__ int    g_boff[NB_SCAN];

// ---------------- CSR build ----------------
__global__ void zero_deg_kernel() {
    int i = blockIdx.x * blockDim.x + threadIdx.x;
    if (i < NN) g_deg[i] = 0;
}

__global__ void count_deg_kernel(const int* __restrict__ ei) {
    int e = blockIdx.x * blockDim.x + threadIdx.x;
    if (e < EE) atomicAdd(&g_deg[ei[EE + e]], 1);
}

__global__ void scanA_kernel() {
    __shared__ int sh[1024];
    int gid = blockIdx.x * 1024 + threadIdx.x;
    int v = (gid < NN) ? g_deg[gid] : 0;
    if (gid < NN) g_dinv[gid] = rsqrtf((float)(v + 1));
    sh[threadIdx.x] = v;
    __syncthreads();
    #pragma unroll
    for (int off = 1; off < 1024; off <<= 1) {
        int t = (threadIdx.x >= off) ? sh[threadIdx.x - off] : 0;
        __syncthreads();
        sh[threadIdx.x] += t;
        __syncthreads();
    }
    if (gid < NN) g_rowptr[gid] = sh[threadIdx.x] - v;
    if (threadIdx.x == 1023) g_bsum[blockIdx.x] = sh[1023];
}

__global__ void scanB_kernel() {
    __shared__ int sh[128];
    int t = threadIdx.x;
    int v = (t < NB_SCAN) ? g_bsum[t] : 0;
    sh[t] = v;
    __syncthreads();
    #pragma unroll
    for (int off = 1; off < 128; off <<= 1) {
        int u = (t >= off) ? sh[t - off] : 0;
        __syncthreads();
        sh[t] += u;
        __syncthreads();
    }
    if (t < NB_SCAN) g_boff[t] = sh[t] - v;
}

__global__ void scanC_kernel() {
    int gid = blockIdx.x * 1024 + threadIdx.x;
    if (gid < NN) {
        int r = g_rowptr[gid] + g_boff[blockIdx.x];
        g_rowptr[gid] = r;
        g_cursor[gid] = r;
    }
    if (gid == 0) g_rowptr[NN] = EE;
}

__global__ void scatter_kernel(const int* __restrict__ ei) {
    int e = blockIdx.x * blockDim.x + threadIdx.x;
    if (e < EE) {
        int s = ei[e];
        int d = ei[EE + e];
        int pos = atomicAdd(&g_cursor[d], 1);
        float w = g_dinv[s] * g_dinv[d];
        g_edge[pos] = make_int2(s, __float_as_int(w));
    }
}

// ------ Tiled GEMM: g_h0h[N,64](fp16) = X[N,K](fp32) @ W[K,64] -----------
// BM=128 rows/block, 128 threads, 8x8 micro-tile.
// smem: Ws (K*32 u64) then Xs (128 x (K+1) floats, padded row).
template <int K, bool FROM_EXT>
__global__ __launch_bounds__(128) void gemm_kernel(const float* __restrict__ X,
                                                   const float* __restrict__ W) {
    extern __shared__ char smem_raw[];
    u64t*  Ws = reinterpret_cast<u64t*>(smem_raw);
    float* Xs = reinterpret_cast<float*>(smem_raw + (size_t)K * 32 * 8);
    const int XS_LD = K + 1;

    int tid = threadIdx.x;

    // load W (K*64 floats = K*32 u64), coalesced
    {
        const u64t* Wg = reinterpret_cast<const u64t*>(W);
        #pragma unroll
        for (int i = tid; i < K * 32; i += 128) Ws[i] = Wg[i];
    }
    // load X tile rows [blockIdx.x*128, +128), coalesced floats -> padded rows
    {
        const float* xb =
            (FROM_EXT ? X : (const float*)g_h1) + (size_t)blockIdx.x * 128 * K;
        #pragma unroll
        for (int i = tid; i < 128 * K; i += 128) {
            int r = i / K;
            int k = i - r * K;
            Xs[r * XS_LD + k] = xb[i];
        }
    }
    __syncthreads();

    int colg = tid & 7;        // 8 col groups x 8 cols
    int rowg = tid >> 3;       // 16 row groups x 8 rows

    u64t acc[32];              // [r][c2]: 8 rows x 4 u64 (8 cols)
    #pragma unroll
    for (int j = 0; j < 32; j++) acc[j] = 0ull;

    const float* xrow = Xs + rowg * 8 * XS_LD;
    const ulonglong2* wsp =
        reinterpret_cast<const ulonglong2*>(Ws + colg * 4);

    #pragma unroll 4
    for (int k = 0; k < K; k++) {
        ulonglong2 wa = wsp[k * 16];       // Ws[k*32 + colg*4 + 0..1]
        ulonglong2 wb = wsp[k * 16 + 1];   // Ws[k*32 + colg*4 + 2..3]
        #pragma unroll
        for (int r = 0; r < 8; r++) {
            u64t xd = dup2(xrow[r * XS_LD + k]);
            acc[r * 4 + 0] = fma2(wa.x, xd, acc[r * 4 + 0]);
            acc[r * 4 + 1] = fma2(wa.y, xd, acc[r * 4 + 1]);
            acc[r * 4 + 2] = fma2(wb.x, xd, acc[r * 4 + 2]);
            acc[r * 4 + 3] = fma2(wb.y, xd, acc[r * 4 + 3]);
        }
    }

    // epilogue: fp16 convert, 16B per row
    size_t rowbase = (size_t)blockIdx.x * 128 + rowg * 8;
    #pragma unroll
    for (int r = 0; r < 8; r++) {
        unsigned h[4];
        #pragma unroll
        for (int p = 0; p < 4; p++) {
            unsigned lo, hi;
            asm("mov.b64 {%0, %1}, %2;" : "=r"(lo), "=r"(hi) : "l"(acc[r * 4 + p]));
            __half2 hh = __floats2half2_rn(__uint_as_float(lo), __uint_as_float(hi));
            h[p] = *reinterpret_cast<unsigned*>(&hh);
        }
        uint4 o = make_uint4(h[0], h[1], h[2], h[3]);
        *reinterpret_cast<uint4*>(
            reinterpret_cast<char*>(g_h0h) + (rowbase + r) * 128 + colg * 16) = o;
    }
}

// ---------------- aggregation: warp/node, fp16 gather -> fp32 acc ----------
__global__ void aggregate_kernel(const float* __restrict__ bias, int relu) {
    int node = blockIdx.x * (blockDim.x >> 5) + (threadIdx.x >> 5);
    int lane = threadIdx.x & 31;
    if (node >= NN) return;

    float dn = g_dinv[node];
    float sw = dn * dn;
    float2 self = __half22float2(g_h0h[(size_t)node * 32 + lane]);
    float ax = sw * self.x;
    float ay = sw * self.y;

    int beg = g_rowptr[node];
    int end = g_rowptr[node + 1];
    #pragma unroll 4
    for (int e = beg; e < end; e++) {
        int2   ed = __ldg(&g_edge[e]);
        float  ww = __int_as_float(ed.y);
        float2 hv = __half22float2(g_h0h[(size_t)ed.x * 32 + lane]);
        ax += ww * hv.x;
        ay += ww * hv.y;
    }

    float2 bv = reinterpret_cast<const float2*>(bias)[lane];
    ax += bv.x;
    ay += bv.y;
    if (relu) { ax = fmaxf(ax, 0.f); ay = fmaxf(ay, 0.f); }
    reinterpret_cast<float2*>(g_h1)[(size_t)node * 32 + lane] =
        make_float2(ax, ay);
}

// ---------------- fused pooling + MLP head: one block per graph -----------
__global__ __launch_bounds__(256) void pool_head_kernel(
        const int* __restrict__ batch,
        const float* __restrict__ lin1_w, const float* __restrict__ lin1_b,
        const float* __restrict__ lin2_w, const float* __restrict__ lin2_b,
        const float* __restrict__ lin3_w, const float* __restrict__ lin3_b,
        float* __restrict__ out) {
    int g = blockIdx.x;
    int tid = threadIdx.x;
    __shared__ int s_se[2];

    // binary search for range [start, end) of nodes with batch == g
    if (tid < 2) {
        int target = g + tid;
        int lo = 0, hi = NN;
        while (lo < hi) {
            int mid = (lo + hi) >> 1;
            if (__ldg(&batch[mid]) < target) lo = mid + 1;
            else hi = mid;
        }
        s_se[tid] = lo;
    }
    __syncthreads();
    int start = s_se[0], end = s_se[1];

    int sub = tid >> 6;   // 0..3
    int d   = tid & 63;

    float sum = 0.f, mx = -FLT_MAX;
    for (int n = start + sub; n < end; n += 4) {
        float v = g_h1[(size_t)n * 64 + d];
        sum += v;
        mx = fmaxf(mx, v);
    }

    __shared__ float ssum[4][64];
    __shared__ float smax[4][64];
    __shared__ float feat[128];
    __shared__ float s1[64];
    __shared__ float s2[64];
    __shared__ float red[64];

    ssum[sub][d] = sum;
    smax[sub][d] = mx;
    __syncthreads();

    if (tid < 64) {
        feat[d]      = ssum[0][d] + ssum[1][d] + ssum[2][d] + ssum[3][d];
        feat[64 + d] = fmaxf(fmaxf(smax[0][d], smax[1][d]),
                             fmaxf(smax[2][d], smax[3][d]));
    }
    __syncthreads();

    if (tid < 64) {
        float a = lin1_b[d];
        #pragma unroll 8
        for (int k = 0; k < 128; k++) a += feat[k] * lin1_w[k * 64 + d];
        s1[d] = fmaxf(a, 0.f);
    }
    __syncthreads();
    if (tid < 64) {
        float b = lin2_b[d];
        #pragma unroll 8
        for (int k = 0; k < 64; k++) b += s1[k] * lin2_w[k * 64 + d];
        s2[d] = fmaxf(b, 0.f);
        red[d] = s2[d] * lin3_w[d];
    }
    __syncthreads();
    if (tid < 32) {
        float v = red[tid] + red[tid + 32];
        #pragma unroll
        for (int off = 16; off > 0; off >>= 1)
            v += __shfl_down_sync(0xFFFFFFFF, v, off);
        if (tid == 0) out[g] = v + lin3_b[0];
    }
}

// ---------------- launch ----------------
#define SMEM_G64  (64 * 32 * 8 + 128 * 65 * 4)
#define SMEM_G128 (128 * 32 * 8 + 128 * 129 * 4)

extern "C" void kernel_launch(void* const* d_in, const int* in_sizes, int n_in,
                              void* d_out, int out_size) {
    const float* x      = (const float*)d_in[0];
    const int*   ei     = (const int*)d_in[1];
    const int*   batch  = (const int*)d_in[2];
    const float* W_in   = (const float*)d_in[3];
    const float* b_in   = (const float*)d_in[4];
    const float* W_hid  = (const float*)d_in[5];
    const float* b_hid  = (const float*)d_in[6];
    const float* lin1_w = (const float*)d_in[7];
    const float* lin1_b = (const float*)d_in[8];
    const float* lin2_w = (const float*)d_in[9];
    const float* lin2_b = (const float*)d_in[10];
    const float* lin3_w = (const float*)d_in[11];
    const float* lin3_b = (const float*)d_in[12];
    float* out = (float*)d_out;

    cudaFuncSetAttribute(gemm_kernel<CINC, true>,
                         cudaFuncAttributeMaxDynamicSharedMemorySize, SMEM_G128);
    cudaFuncSetAttribute(gemm_kernel<DD, false>,
                         cudaFuncAttributeMaxDynamicSharedMemorySize, SMEM_G64);

    // CSR build
    zero_deg_kernel<<<(NN + 255) / 256, 256>>>();
    count_deg_kernel<<<(EE + 255) / 256, 256>>>(ei);
    scanA_kernel<<<NB_SCAN, 1024>>>();
    scanB_kernel<<<1, 128>>>();
    scanC_kernel<<<NB_SCAN, 1024>>>();
    scatter_kernel<<<(EE + 255) / 256, 256>>>(ei);

    const int gemm_blocks = NN / 128;        // 625, exact
    const int agg_blocks  = (NN + 7) / 8;

    // layer 0
    gemm_kernel<CINC, true><<<gemm_blocks, 128, SMEM_G128>>>(x, W_in);
    aggregate_kernel<<<agg_blocks, 256>>>(b_in, 1);

    // hidden layers
    for (int i = 0; i < NHID; i++) {
        gemm_kernel<DD, false><<<gemm_blocks, 128, SMEM_G64>>>(
            nullptr, W_hid + (size_t)i * DD * DD);
        aggregate_kernel<<<agg_blocks, 256>>>(b_hid + (size_t)i * DD,
                                              (i < NHID - 1) ? 1 : 0);
    }

    // fused pooling + head
    pool_head_kernel<<<GG, 256>>>(batch, lin1_w, lin1_b, lin2_w, lin2_b,
                                  lin3_w, lin3_b, out);
}